// round 9
// baseline (speedup 1.0000x reference)
#include <cuda_runtime.h>

#define IC 1152
#define OC 10
#define ID 8
#define OD 16
#define OD2 8          // packed f32x2 pairs
#define BATCH 32
#define NITER 5
#define EPSV 1e-20f
#define ICPB 8         // ics per block, processed as 4 pairs (2 in flight)
#define NPAIR (ICPB / 2)
#define NTHREADS 320   // 10 warps: warp = oc, lane = b
#define WSLAB (OC * ID * OD)   // 1280 floats per ic

typedef unsigned long long u64;

__device__ __forceinline__ u64 pk2(float lo, float hi) {
    u64 r; asm("mov.b64 %0, {%1,%2};" : "=l"(r) : "f"(lo), "f"(hi)); return r;
}
__device__ __forceinline__ float2 upk2(u64 v) {
    float2 f; asm("mov.b64 {%0,%1}, %2;" : "=f"(f.x), "=f"(f.y) : "l"(v)); return f;
}
__device__ __forceinline__ u64 mul2(u64 a, u64 b) {
    u64 r; asm("mul.rn.f32x2 %0, %1, %2;" : "=l"(r) : "l"(a), "l"(b)); return r;
}
__device__ __forceinline__ u64 add2(u64 a, u64 b) {
    u64 r; asm("add.rn.f32x2 %0, %1, %2;" : "=l"(r) : "l"(a), "l"(b)); return r;
}
__device__ __forceinline__ u64 fma2(u64 a, u64 b, u64 c) {
    u64 r; asm("fma.rn.f32x2 %0, %1, %2, %3;" : "=l"(r) : "l"(a), "l"(b), "l"(c)); return r;
}
__device__ __forceinline__ unsigned smem_u32(const void* p) {
    return (unsigned)__cvta_generic_to_shared(p);
}
__device__ __forceinline__ void cp_async16(unsigned dst, const void* src) {
    asm volatile("cp.async.ca.shared.global [%0], [%1], 16;" :: "r"(dst), "l"(src));
}

__global__ void zero_out_kernel(float* out, int n) {
    int i = blockIdx.x * blockDim.x + threadIdx.x;
    if (i < n) out[i] = 0.0f;
}

__global__ __launch_bounds__(NTHREADS, 1)
void caps_kernel(const float* __restrict__ x,
                 const float* __restrict__ w,
                 float* __restrict__ out) {
    __shared__ __align__(16) float w_s[2][2][WSLAB];   // [buf][slab-in-pair]
    __shared__ float x_s[ICPB][BATCH][ID + 1];         // padded stride 9
    __shared__ float alpha_s[2][BATCH][OC];

    const int tid = threadIdx.x;
    const int b   = tid & 31;     // lane
    const int oc  = tid >> 5;     // warp
    const int ic0 = blockIdx.x * ICPB;

    // ---- load all x for this block's 8 ics (once) ----
    for (int i = tid; i < ICPB * BATCH * ID; i += NTHREADS) {
        int kk = i >> 8;            // ic within block
        int rem = i & 255;
        int bb = rem >> 3, id = rem & 7;
        x_s[kk][bb][id] = x[(bb * IC + ic0 + kk) * ID + id];
    }
    // ---- cp.async pair 0 into buf 0 (2 slabs = 2560 floats = 640 float4) ----
    {
        const float4* src = (const float4*)(w + (size_t)ic0 * WSLAB);
        float4* dst = (float4*)&w_s[0][0][0];
        cp_async16(smem_u32(dst + tid), src + tid);
        cp_async16(smem_u32(dst + tid + NTHREADS), src + tid + NTHREADS);
        asm volatile("cp.async.commit_group;");
    }
    asm volatile("cp.async.wait_group 0;");
    __syncthreads();

    for (int p = 0; p < NPAIR; p++) {
        const int buf = p & 1;

        // ---- prefetch next pair into the other buffer (async, no regs) ----
        if (p + 1 < NPAIR) {
            const float4* src = (const float4*)(w + (size_t)(ic0 + 2 * (p + 1)) * WSLAB);
            float4* dst = (float4*)&w_s[buf ^ 1][0][0];
            cp_async16(smem_u32(dst + tid), src + tid);
            cp_async16(smem_u32(dst + tid + NTHREADS), src + tid + NTHREADS);
            asm volatile("cp.async.commit_group;");
        }

        // ---- xn for both ics of the pair ----
        float xn[2][ID];
#pragma unroll
        for (int pp = 0; pp < 2; pp++) {
            float xs = 0.0f;
#pragma unroll
            for (int id = 0; id < ID; id++) {
                xn[pp][id] = x_s[2 * p + pp][b][id];
                xs += xn[pp][id];
            }
            float xr = __fdividef(1.0f, xs + EPSV);
#pragma unroll
            for (int id = 0; id < ID; id++) xn[pp][id] *= xr;
        }

        const u64* wq[2] = {
            (const u64*)(&w_s[buf][0][0] + oc * ID * OD),
            (const u64*)(&w_s[buf][1][0] + oc * ID * OD)
        };

        // ---- NNMF, factored form, TWO independent streams interleaved ----
        u64 outv2[2][OD2];
#pragma unroll
        for (int pp = 0; pp < 2; pp++)
#pragma unroll
            for (int j = 0; j < OD2; j++) outv2[pp][j] = pk2(1.0f / OD, 1.0f / OD);

#pragma unroll
        for (int it = 0; it < NITER; it++) {
            // phase 1: 16 independent dot chains
            float s[2][ID];
#pragma unroll
            for (int pp = 0; pp < 2; pp++)
#pragma unroll
                for (int id = 0; id < ID; id++) {
                    u64 acc = mul2(outv2[pp][0], wq[pp][id * OD2 + 0]);
#pragma unroll
                    for (int j = 1; j < OD2; j++)
                        acc = fma2(outv2[pp][j], wq[pp][id * OD2 + j], acc);
                    float2 f = upk2(acc);
                    s[pp][id] = f.x + f.y;
                }
            // phase 2: 16 pipelined reciprocals
#pragma unroll
            for (int pp = 0; pp < 2; pp++)
#pragma unroll
                for (int id = 0; id < ID; id++)
                    s[pp][id] = __fdividef(xn[pp][id], s[pp][id] + EPSV);
            // phase 3: 16 independent column chains
#pragma unroll
            for (int pp = 0; pp < 2; pp++) {
                u64 t[OD2];
                {
                    u64 sp = pk2(s[pp][0], s[pp][0]);
#pragma unroll
                    for (int j = 0; j < OD2; j++) t[j] = mul2(sp, wq[pp][j]);
                }
#pragma unroll
                for (int id = 1; id < ID; id++) {
                    u64 sp = pk2(s[pp][id], s[pp][id]);
#pragma unroll
                    for (int j = 0; j < OD2; j++)
                        t[j] = fma2(sp, wq[pp][id * OD2 + j], t[j]);
                }
#pragma unroll
                for (int j = 0; j < OD2; j++)
                    outv2[pp][j] = mul2(outv2[pp][j], t[j]);
            }
        }

        // ---- final normalization + alpha, per stream ----
        float alpha[2];
#pragma unroll
        for (int pp = 0; pp < 2; pp++) {
            u64 t01 = add2(outv2[pp][0], outv2[pp][1]);
            u64 t23 = add2(outv2[pp][2], outv2[pp][3]);
            u64 t45 = add2(outv2[pp][4], outv2[pp][5]);
            u64 t67 = add2(outv2[pp][6], outv2[pp][7]);
            float2 tf = upk2(add2(add2(t01, t23), add2(t45, t67)));
            float rn = __fdividef(1.0f, tf.x + tf.y + EPSV);
            u64 rn2 = pk2(rn, rn);
#pragma unroll
            for (int j = 0; j < OD2; j++) outv2[pp][j] = mul2(outv2[pp][j], rn2);

            float a = 0.0f;
#pragma unroll
            for (int id = 0; id < ID; id++) {
                u64 acc = mul2(outv2[pp][0], wq[pp][id * OD2 + 0]);
#pragma unroll
                for (int j = 1; j < OD2; j++)
                    acc = fma2(outv2[pp][j], wq[pp][id * OD2 + j], acc);
                float2 rf = upk2(acc);
                a = fmaf(rf.x + rf.y, xn[pp][id], a);
            }
            alpha[pp] = a;
        }

        alpha_s[0][b][oc] = alpha[0];
        alpha_s[1][b][oc] = alpha[1];
        __syncthreads();   // alpha visible; all w_s[buf]/x_s reads done

        float an[2];
#pragma unroll
        for (int pp = 0; pp < 2; pp++) {
            float asum = 0.0f;
#pragma unroll
            for (int o2 = 0; o2 < OC; o2++) asum += alpha_s[pp][b][o2];
            an[pp] = alpha[pp] * __fdividef(1.0f, asum + EPSV);
        }

        // ---- flush combined pair contribution ----
        u64 an0 = pk2(an[0], an[0]), an1 = pk2(an[1], an[1]);
        float* ob = &out[(b * OC + oc) * OD];
#pragma unroll
        for (int j = 0; j < OD2; j++) {
            u64 c = fma2(outv2[1][j], an1, mul2(outv2[0][j], an0));
            float2 f = upk2(c);
            atomicAdd(ob + 2 * j,     f.x);
            atomicAdd(ob + 2 * j + 1, f.y);
        }

        // ---- next pair: wait for its weights, fence alpha_s reuse ----
        if (p + 1 < NPAIR)
            asm volatile("cp.async.wait_group 0;");
        __syncthreads();
    }
}

extern "C" void kernel_launch(void* const* d_in, const int* in_sizes, int n_in,
                              void* d_out, int out_size) {
    const float* x = (const float*)d_in[0];   // [32, 1152, 8]
    const float* w = (const float*)d_in[1];   // [1152, 10, 8, 16]
    float* out = (float*)d_out;               // [32, 10, 16]

    zero_out_kernel<<<(BATCH * OC * OD + 255) / 256, 256>>>(out, BATCH * OC * OD);
    caps_kernel<<<IC / ICPB, NTHREADS>>>(x, w, out);   // grid = 144 = one wave
}

// round 10
// speedup vs baseline: 1.0867x; 1.0867x over previous
#include <cuda_runtime.h>

#define IC 1152
#define OC 10
#define ID 8
#define OD 16
#define OD2 8          // packed f32x2 pairs
#define BATCH 32
#define NITER 5
#define EPSV 1e-20f
#define ICPB 4
#define NTHREADS 320   // 10 warps: warp = oc, lane = b
#define WSLAB (OC * ID * OD)   // 1280 floats per ic

typedef unsigned long long u64;

__device__ __forceinline__ u64 pk2(float lo, float hi) {
    u64 r; asm("mov.b64 %0, {%1,%2};" : "=l"(r) : "f"(lo), "f"(hi)); return r;
}
__device__ __forceinline__ float2 upk2(u64 v) {
    float2 f; asm("mov.b64 {%0,%1}, %2;" : "=f"(f.x), "=f"(f.y) : "l"(v)); return f;
}
__device__ __forceinline__ u64 mul2(u64 a, u64 b) {
    u64 r; asm("mul.rn.f32x2 %0, %1, %2;" : "=l"(r) : "l"(a), "l"(b)); return r;
}
__device__ __forceinline__ u64 add2(u64 a, u64 b) {
    u64 r; asm("add.rn.f32x2 %0, %1, %2;" : "=l"(r) : "l"(a), "l"(b)); return r;
}
__device__ __forceinline__ u64 fma2(u64 a, u64 b, u64 c) {
    u64 r; asm("fma.rn.f32x2 %0, %1, %2, %3;" : "=l"(r) : "l"(a), "l"(b), "l"(c)); return r;
}

__global__ void zero_out_kernel(float* out, int n) {
    int i = blockIdx.x * blockDim.x + threadIdx.x;
    if (i < n) out[i] = 0.0f;
}

__global__ __launch_bounds__(NTHREADS, 1)   // no reg cap: 1 CTA/SM, zero spills
void caps_kernel(const float* __restrict__ x,
                 const float* __restrict__ w,
                 float* __restrict__ out) {
    __shared__ __align__(16) float w_s[WSLAB];      // current ic weight slab
    __shared__ float x_s[BATCH][ID + 1];            // padded: stride 9
    __shared__ float alpha_s[BATCH][OC];

    const int tid = threadIdx.x;
    const int b   = tid & 31;     // lane
    const int oc  = tid >> 5;     // warp

    u64 res2[OD2];
#pragma unroll
    for (int j = 0; j < OD2; j++) res2[j] = 0ull;

    // ---- load slab 0 ----
    {
        const int ic0 = blockIdx.x * ICPB;
        for (int i = tid; i < WSLAB; i += NTHREADS)
            w_s[i] = w[ic0 * WSLAB + i];
        if (tid < BATCH * ID) {
            int bb = tid >> 3, id = tid & 7;
            x_s[bb][id] = x[(bb * IC + ic0) * ID + id];
        }
    }
    __syncthreads();

    for (int k = 0; k < ICPB; k++) {
        const int ic = blockIdx.x * ICPB + k;

        // ---- register-prefetch next slab (hidden behind compute) ----
        float wpre0 = 0.f, wpre1 = 0.f, wpre2 = 0.f, wpre3 = 0.f, xpre = 0.f;
        if (k + 1 < ICPB) {
            const float* wn = w + (ic + 1) * WSLAB;
            wpre0 = wn[tid];
            wpre1 = wn[tid + NTHREADS];
            wpre2 = wn[tid + 2 * NTHREADS];
            wpre3 = wn[tid + 3 * NTHREADS];
            if (tid < BATCH * ID)
                xpre = x[((tid >> 3) * IC + ic + 1) * ID + (tid & 7)];
        }

        // ---- normalize x over ID ----
        float xn[ID];
        float xs = 0.0f;
#pragma unroll
        for (int id = 0; id < ID; id++) { xn[id] = x_s[b][id]; xs += xn[id]; }
        float xr = __fdividef(1.0f, xs + EPSV);
#pragma unroll
        for (int id = 0; id < ID; id++) xn[id] *= xr;

        // weight rows as 128-bit vectors: 4 ulonglong2 per id row (16 floats)
        const ulonglong2* wv = reinterpret_cast<const ulonglong2*>(w_s + oc * ID * OD);

        // ---- NNMF, factored + FUSED: each weight touched once per iter.
        //   per id: load row → d = Σ_j outv[j]·w[id][j] → s = xn[id]/(d+ε)
        //           → t[j] += s·w[id][j]   (same regs)
        //   outv[j] *= t[j] after the id loop.
        // per-iteration normalization is scale-invariant; applied once ----
        u64 outv2[OD2];
#pragma unroll
        for (int j = 0; j < OD2; j++) outv2[j] = pk2(1.0f / OD, 1.0f / OD);

#pragma unroll
        for (int it = 0; it < NITER; it++) {
            u64 t[OD2];
#pragma unroll
            for (int j = 0; j < OD2; j++) t[j] = 0ull;

#pragma unroll
            for (int id = 0; id < ID; id++) {
                ulonglong2 q0 = wv[id * 4 + 0];
                ulonglong2 q1 = wv[id * 4 + 1];
                ulonglong2 q2 = wv[id * 4 + 2];
                ulonglong2 q3 = wv[id * 4 + 3];
                // dot with outv (2 parallel half-chains)
                u64 a0 = mul2(outv2[0], q0.x);
                u64 a1 = mul2(outv2[1], q0.y);
                a0 = fma2(outv2[2], q1.x, a0);
                a1 = fma2(outv2[3], q1.y, a1);
                a0 = fma2(outv2[4], q2.x, a0);
                a1 = fma2(outv2[5], q2.y, a1);
                a0 = fma2(outv2[6], q3.x, a0);
                a1 = fma2(outv2[7], q3.y, a1);
                float2 f = upk2(add2(a0, a1));
                float s = __fdividef(xn[id], f.x + f.y + EPSV);
                u64 sp = pk2(s, s);
                // reuse the loaded row for the column accumulation
                t[0] = fma2(sp, q0.x, t[0]);
                t[1] = fma2(sp, q0.y, t[1]);
                t[2] = fma2(sp, q1.x, t[2]);
                t[3] = fma2(sp, q1.y, t[3]);
                t[4] = fma2(sp, q2.x, t[4]);
                t[5] = fma2(sp, q2.y, t[5]);
                t[6] = fma2(sp, q3.x, t[6]);
                t[7] = fma2(sp, q3.y, t[7]);
            }
#pragma unroll
            for (int j = 0; j < OD2; j++)
                outv2[j] = mul2(outv2[j], t[j]);
        }

        // ---- final normalization over OD (needed before alpha mixes oc) ----
        {
            u64 t01 = add2(outv2[0], outv2[1]), t23 = add2(outv2[2], outv2[3]);
            u64 t45 = add2(outv2[4], outv2[5]), t67 = add2(outv2[6], outv2[7]);
            float2 tf = upk2(add2(add2(t01, t23), add2(t45, t67)));
            float rn = __fdividef(1.0f, tf.x + tf.y + EPSV);
            u64 rn2 = pk2(rn, rn);
#pragma unroll
            for (int j = 0; j < OD2; j++) outv2[j] = mul2(outv2[j], rn2);
        }

        // ---- reconstruct + alpha (vector loads, fused) ----
        float alpha = 0.0f;
#pragma unroll
        for (int id = 0; id < ID; id++) {
            ulonglong2 q0 = wv[id * 4 + 0];
            ulonglong2 q1 = wv[id * 4 + 1];
            ulonglong2 q2 = wv[id * 4 + 2];
            ulonglong2 q3 = wv[id * 4 + 3];
            u64 a0 = mul2(outv2[0], q0.x);
            u64 a1 = mul2(outv2[1], q0.y);
            a0 = fma2(outv2[2], q1.x, a0);
            a1 = fma2(outv2[3], q1.y, a1);
            a0 = fma2(outv2[4], q2.x, a0);
            a1 = fma2(outv2[5], q2.y, a1);
            a0 = fma2(outv2[6], q3.x, a0);
            a1 = fma2(outv2[7], q3.y, a1);
            float2 rf = upk2(add2(a0, a1));
            alpha = fmaf(rf.x + rf.y, xn[id], alpha);
        }

        alpha_s[b][oc] = alpha;
        __syncthreads();   // alpha visible; all w_s/x_s reads complete

        // ---- store prefetched slab (w_s/x_s no longer read this k) ----
        if (k + 1 < ICPB) {
            w_s[tid]                = wpre0;
            w_s[tid + NTHREADS]     = wpre1;
            w_s[tid + 2 * NTHREADS] = wpre2;
            w_s[tid + 3 * NTHREADS] = wpre3;
            if (tid < BATCH * ID)
                x_s[tid >> 3][tid & 7] = xpre;
        }

        float asum = 0.0f;
#pragma unroll
        for (int o2 = 0; o2 < OC; o2++) asum += alpha_s[b][o2];
        float an = alpha * __fdividef(1.0f, asum + EPSV);
        u64 an2 = pk2(an, an);
#pragma unroll
        for (int j = 0; j < OD2; j++)
            res2[j] = fma2(outv2[j], an2, res2[j]);

        __syncthreads();   // new slab visible + alpha_s reads complete
    }

    // ---- accumulate over ic (288 adds per address — cheap) ----
#pragma unroll
    for (int j = 0; j < OD2; j++) {
        float2 f = upk2(res2[j]);
        atomicAdd(&out[(b * OC + oc) * OD + 2 * j],     f.x);
        atomicAdd(&out[(b * OC + oc) * OD + 2 * j + 1], f.y);
    }
}

extern "C" void kernel_launch(void* const* d_in, const int* in_sizes, int n_in,
                              void* d_out, int out_size) {
    const float* x = (const float*)d_in[0];   // [32, 1152, 8]
    const float* w = (const float*)d_in[1];   // [1152, 10, 8, 16]
    float* out = (float*)d_out;               // [32, 10, 16]

    zero_out_kernel<<<(BATCH * OC * OD + 255) / 256, 256>>>(out, BATCH * OC * OD);
    caps_kernel<<<IC / ICPB, NTHREADS>>>(x, w, out);
}

// round 12
// speedup vs baseline: 1.1873x; 1.0926x over previous
#include <cuda_runtime.h>

#define IC 1152
#define OC 10
#define ID 8
#define OD 16
#define OD4 4          // packed f32x2 pairs per od-half
#define BATCH 32
#define NITER 5
#define EPSV 1e-20f
#define ICPB 8
#define NTHREADS 640   // 20 warps: warp=(oc,b-half), lane=odh*16+b%16
#define WSLAB (OC * ID * OD)   // 1280 floats per ic

typedef unsigned long long u64;

__device__ __forceinline__ u64 pk2(float lo, float hi) {
    u64 r; asm("mov.b64 %0, {%1,%2};" : "=l"(r) : "f"(lo), "f"(hi)); return r;
}
__device__ __forceinline__ float2 upk2(u64 v) {
    float2 f; asm("mov.b64 {%0,%1}, %2;" : "=f"(f.x), "=f"(f.y) : "l"(v)); return f;
}
__device__ __forceinline__ u64 mul2(u64 a, u64 b) {
    u64 r; asm("mul.rn.f32x2 %0, %1, %2;" : "=l"(r) : "l"(a), "l"(b)); return r;
}
__device__ __forceinline__ u64 add2(u64 a, u64 b) {
    u64 r; asm("add.rn.f32x2 %0, %1, %2;" : "=l"(r) : "l"(a), "l"(b)); return r;
}
__device__ __forceinline__ u64 fma2(u64 a, u64 b, u64 c) {
    u64 r; asm("fma.rn.f32x2 %0, %1, %2, %3;" : "=l"(r) : "l"(a), "l"(b), "l"(c)); return r;
}

__global__ void zero_out_kernel(float* out, int n) {
    int i = blockIdx.x * blockDim.x + threadIdx.x;
    if (i < n) out[i] = 0.0f;
}

__global__ __launch_bounds__(NTHREADS, 1)
void caps_kernel(const float* __restrict__ x,
                 const float* __restrict__ w,
                 float* __restrict__ out) {
    __shared__ __align__(16) float w_s[WSLAB];
    __shared__ float x_s[BATCH][ID + 1];            // stride 9: conflict-free
    __shared__ float alpha_s[BATCH][OC];

    const int tid  = threadIdx.x;
    const int lane = tid & 31;
    const int warp = tid >> 5;                      // 0..19
    const int oc   = warp >> 1;                     // warp pair -> oc
    const int b    = ((warp & 1) << 4) | (lane & 15);
    const int odh  = lane >> 4;                     // od half: 0 or 1

    u64 res2[OD4];
#pragma unroll
    for (int j = 0; j < OD4; j++) res2[j] = 0ull;

    // ---- load slab 0 + x for ic0 ----
    {
        const int ic0 = blockIdx.x * ICPB;
        w_s[tid]            = w[ic0 * WSLAB + tid];
        w_s[tid + NTHREADS] = w[ic0 * WSLAB + tid + NTHREADS];
        if (tid < BATCH * ID) {
            int bb = tid >> 3, id = tid & 7;
            x_s[bb][id] = x[(bb * IC + ic0) * ID + id];
        }
    }
    __syncthreads();

    for (int k = 0; k < ICPB; k++) {
        const int ic = blockIdx.x * ICPB + k;

        // ---- register-prefetch next slab (2 regs) ----
        float wpre0 = 0.f, wpre1 = 0.f, xpre = 0.f;
        if (k + 1 < ICPB) {
            const float* wn = w + (size_t)(ic + 1) * WSLAB;
            wpre0 = wn[tid];
            wpre1 = wn[tid + NTHREADS];
            if (tid < BATCH * ID)
                xpre = x[((tid >> 3) * IC + ic + 1) * ID + (tid & 7)];
        }

        // ---- normalize x over ID ----
        float xn[ID];
        float xs = 0.0f;
#pragma unroll
        for (int id = 0; id < ID; id++) { xn[id] = x_s[b][id]; xs += xn[id]; }
        float xr = __fdividef(1.0f, xs + EPSV);
#pragma unroll
        for (int id = 0; id < ID; id++) xn[id] *= xr;

        // this thread's od-half of each weight row: 2 ulonglong2 per id
        const ulonglong2* wv =
            reinterpret_cast<const ulonglong2*>(w_s + oc * ID * OD) + odh * 2;

        // ---- NNMF factored, OD split across lane pairs:
        //   half-dot per id -> shfl.xor(16) combine -> rcp -> half column sums
        u64 outv2[OD4];
#pragma unroll
        for (int j = 0; j < OD4; j++) outv2[j] = pk2(1.0f / OD, 1.0f / OD);

#pragma unroll
        for (int it = 0; it < NITER; it++) {
            // phase 1: 8 independent half-dots
            float s[ID];
#pragma unroll
            for (int id = 0; id < ID; id++) {
                ulonglong2 q0 = wv[id * 4];
                ulonglong2 q1 = wv[id * 4 + 1];
                u64 a0 = mul2(outv2[0], q0.x);
                u64 a1 = mul2(outv2[1], q0.y);
                a0 = fma2(outv2[2], q1.x, a0);
                a1 = fma2(outv2[3], q1.y, a1);
                float2 f = upk2(add2(a0, a1));
                s[id] = f.x + f.y;
            }
            // phase 2: batched partner-combines + reciprocals
#pragma unroll
            for (int id = 0; id < ID; id++) {
                float tot = s[id] + __shfl_xor_sync(0xFFFFFFFFu, s[id], 16);
                s[id] = __fdividef(xn[id], tot + EPSV);
            }
            // phase 3: 4 independent half column chains
            u64 t[OD4];
            {
                u64 sp = pk2(s[0], s[0]);
                t[0] = mul2(sp, wv[0].x);
                t[1] = mul2(sp, wv[0].y);
                t[2] = mul2(sp, wv[1].x);
                t[3] = mul2(sp, wv[1].y);
            }
#pragma unroll
            for (int id = 1; id < ID; id++) {
                u64 sp = pk2(s[id], s[id]);
                ulonglong2 q0 = wv[id * 4];
                ulonglong2 q1 = wv[id * 4 + 1];
                t[0] = fma2(sp, q0.x, t[0]);
                t[1] = fma2(sp, q0.y, t[1]);
                t[2] = fma2(sp, q1.x, t[2]);
                t[3] = fma2(sp, q1.y, t[3]);
            }
#pragma unroll
            for (int j = 0; j < OD4; j++)
                outv2[j] = mul2(outv2[j], t[j]);
        }

        // ---- final normalization over OD (cross-partner) ----
        {
            float2 tf = upk2(add2(add2(outv2[0], outv2[1]),
                                  add2(outv2[2], outv2[3])));
            float loc = tf.x + tf.y;
            float tot = loc + __shfl_xor_sync(0xFFFFFFFFu, loc, 16);
            float rn = __fdividef(1.0f, tot + EPSV);
            u64 rn2 = pk2(rn, rn);
#pragma unroll
            for (int j = 0; j < OD4; j++) outv2[j] = mul2(outv2[j], rn2);
        }

        // ---- reconstruct + alpha (half-dots, one combine at the end) ----
        float ap = 0.0f;
#pragma unroll
        for (int id = 0; id < ID; id++) {
            ulonglong2 q0 = wv[id * 4];
            ulonglong2 q1 = wv[id * 4 + 1];
            u64 a0 = mul2(outv2[0], q0.x);
            u64 a1 = mul2(outv2[1], q0.y);
            a0 = fma2(outv2[2], q1.x, a0);
            a1 = fma2(outv2[3], q1.y, a1);
            float2 rf = upk2(add2(a0, a1));
            ap = fmaf(rf.x + rf.y, xn[id], ap);
        }
        float alpha = ap + __shfl_xor_sync(0xFFFFFFFFu, ap, 16);

        if (odh == 0) alpha_s[b][oc] = alpha;
        __syncthreads();   // alpha visible; all w_s/x_s reads complete

        // ---- store prefetched slab ----
        if (k + 1 < ICPB) {
            w_s[tid]            = wpre0;
            w_s[tid + NTHREADS] = wpre1;
            if (tid < BATCH * ID)
                x_s[tid >> 3][tid & 7] = xpre;
        }

        float asum = 0.0f;
#pragma unroll
        for (int o2 = 0; o2 < OC; o2++) asum += alpha_s[b][o2];
        float an = alpha * __fdividef(1.0f, asum + EPSV);
        u64 an2 = pk2(an, an);
#pragma unroll
        for (int j = 0; j < OD4; j++)
            res2[j] = fma2(outv2[j], an2, res2[j]);

        __syncthreads();   // new slab visible + alpha_s reads complete
    }

    // ---- accumulate over ic (144 adds per address — cheap) ----
    float* ob = &out[(b * OC + oc) * OD + odh * 8];
#pragma unroll
    for (int j = 0; j < OD4; j++) {
        float2 f = upk2(res2[j]);
        atomicAdd(ob + 2 * j,     f.x);
        atomicAdd(ob + 2 * j + 1, f.y);
    }
}

extern "C" void kernel_launch(void* const* d_in, const int* in_sizes, int n_in,
                              void* d_out, int out_size) {
    const float* x = (const float*)d_in[0];   // [32, 1152, 8]
    const float* w = (const float*)d_in[1];   // [1152, 10, 8, 16]
    float* out = (float*)d_out;               // [32, 10, 16]

    zero_out_kernel<<<(BATCH * OC * OD + 255) / 256, 256>>>(out, BATCH * OC * OD);
    caps_kernel<<<IC / ICPB, NTHREADS>>>(x, w, out);   // grid = 144 = one wave
}